// round 12
// baseline (speedup 1.0000x reference)
#include <cuda_runtime.h>
#include <math.h>
#include <cstdint>

#define BB 2
#define NN 2048
#define DM 512
#define NH 8
#define HD 64
#define TOPK 64
#define BH (BB*NH)       // 16
#define M_TOT (BB*NN)    // 4096
#define SCALEF 0.125f

// ---------------- scratch (static __device__ per allocation rules) ----------
__device__ float g_Qh[BH*NN*HD];            // [bh][n][d]  (Q pre-scaled by 1/8)
__device__ float g_Kh[BH*NN*HD];
__device__ float g_Vh[BH*NN*HD];
__device__ float g_S[(size_t)BH*NN*NN];     // raw scores 256MB
__device__ float g_H[M_TOT*DM];             // merged-head attn output

// ---------------------------------------------------------------------------
// 128x128-tile fp32 GEMM, 8x8 micro-tile, BK=16, 256 threads, double-buffered.
// mode 0: fused QKV (head-split out, Q scaled). mode 1: out-proj from g_H.
// (identical to round-5 proven version)
// ---------------------------------------------------------------------------
__global__ __launch_bounds__(256)
void gemm128(const float* __restrict__ X0, const float* __restrict__ X1,
             const float* __restrict__ X2,
             const float* __restrict__ W0, const float* __restrict__ W1,
             const float* __restrict__ W2,
             const float* __restrict__ b0, const float* __restrict__ b1,
             const float* __restrict__ b2,
             float* __restrict__ outp, int mode)
{
    __shared__ float XsT[2][16][132];
    __shared__ float WsT[2][16][132];

    const int tid = threadIdx.x;
    const int tx = tid & 15, ty = tid >> 4;
    const int m0 = blockIdx.y * 128;

    int which = 0, o0 = 0;
    const float *X, *W, *bias;
    if (mode == 0) {
        which = blockIdx.x >> 2;
        o0 = (blockIdx.x & 3) * 128;
        X    = (which == 0) ? X0 : (which == 1) ? X1 : X2;
        W    = (which == 0) ? W0 : (which == 1) ? W1 : W2;
        bias = (which == 0) ? b0 : (which == 1) ? b1 : b2;
    } else {
        o0 = blockIdx.x * 128;
        X = g_H; W = W0; bias = b0;
    }

    const int lr  = tid >> 2;
    const int lc4 = (tid & 3) * 4;

    float acc[8][8];
#pragma unroll
    for (int i = 0; i < 8; i++)
#pragma unroll
        for (int j = 0; j < 8; j++) acc[i][j] = 0.f;

    float4 xr[2], wr[2];
#pragma unroll
    for (int j = 0; j < 2; j++) {
        int r = lr + j * 64;
        xr[j] = *(const float4*)&X[(size_t)(m0 + r) * DM + lc4];
        wr[j] = *(const float4*)&W[(size_t)(o0 + r) * DM + lc4];
    }
#pragma unroll
    for (int j = 0; j < 2; j++) {
        int r = lr + j * 64;
        XsT[0][lc4 + 0][r] = xr[j].x; XsT[0][lc4 + 1][r] = xr[j].y;
        XsT[0][lc4 + 2][r] = xr[j].z; XsT[0][lc4 + 3][r] = xr[j].w;
        WsT[0][lc4 + 0][r] = wr[j].x; WsT[0][lc4 + 1][r] = wr[j].y;
        WsT[0][lc4 + 2][r] = wr[j].z; WsT[0][lc4 + 3][r] = wr[j].w;
    }
    __syncthreads();

    int p = 0;
    for (int k0 = 0; k0 < DM; k0 += 16) {
        const int kn = k0 + 16;
        if (kn < DM) {
#pragma unroll
            for (int j = 0; j < 2; j++) {
                int r = lr + j * 64;
                xr[j] = *(const float4*)&X[(size_t)(m0 + r) * DM + kn + lc4];
                wr[j] = *(const float4*)&W[(size_t)(o0 + r) * DM + kn + lc4];
            }
        }
#pragma unroll
        for (int kk = 0; kk < 16; kk++) {
            float4 a0 = *(const float4*)&XsT[p][kk][ty * 4];
            float4 a1 = *(const float4*)&XsT[p][kk][64 + ty * 4];
            float4 bv0 = *(const float4*)&WsT[p][kk][tx * 4];
            float4 bv1 = *(const float4*)&WsT[p][kk][64 + tx * 4];
            float a[8] = {a0.x, a0.y, a0.z, a0.w, a1.x, a1.y, a1.z, a1.w};
            float b[8] = {bv0.x, bv0.y, bv0.z, bv0.w, bv1.x, bv1.y, bv1.z, bv1.w};
#pragma unroll
            for (int i = 0; i < 8; i++)
#pragma unroll
                for (int j = 0; j < 8; j++) acc[i][j] += a[i] * b[j];
        }
        if (kn < DM) {
            int pn = p ^ 1;
#pragma unroll
            for (int j = 0; j < 2; j++) {
                int r = lr + j * 64;
                XsT[pn][lc4 + 0][r] = xr[j].x; XsT[pn][lc4 + 1][r] = xr[j].y;
                XsT[pn][lc4 + 2][r] = xr[j].z; XsT[pn][lc4 + 3][r] = xr[j].w;
                WsT[pn][lc4 + 0][r] = wr[j].x; WsT[pn][lc4 + 1][r] = wr[j].y;
                WsT[pn][lc4 + 2][r] = wr[j].z; WsT[pn][lc4 + 3][r] = wr[j].w;
            }
        }
        __syncthreads();
        p ^= 1;
    }

    const float sc = (mode == 0 && which == 0) ? SCALEF : 1.f;
#pragma unroll
    for (int i = 0; i < 8; i++) {
        int m = m0 + ((i < 4) ? ty * 4 + i : 64 + ty * 4 + (i - 4));
#pragma unroll
        for (int jg = 0; jg < 2; jg++) {
            int oc = o0 + ((jg == 0) ? tx * 4 : 64 + tx * 4);
            float4 v;
            v.x = (acc[i][jg * 4 + 0] + bias[oc + 0]) * sc;
            v.y = (acc[i][jg * 4 + 1] + bias[oc + 1]) * sc;
            v.z = (acc[i][jg * 4 + 2] + bias[oc + 2]) * sc;
            v.w = (acc[i][jg * 4 + 3] + bias[oc + 3]) * sc;
            if (mode == 0) {
                int b = m >> 11, n = m & (NN - 1);
                int h = oc >> 6, d = oc & 63;
                float* dst = (which == 0) ? g_Qh : (which == 1) ? g_Kh : g_Vh;
                *(float4*)&dst[(size_t)((b * NH + h) * NN + n) * HD + d] = v;
            } else {
                *(float4*)&outp[(size_t)m * DM + oc] = v;
            }
        }
    }
}

// ---------------------------------------------------------------------------
// Scores (round-5 proven, __stcs streaming stores): S = Qh @ Kh^T.
// 128x128 tiles, 8x8 micro-tile, 2 x BK=32 stages. grid (16,16,16).
// ---------------------------------------------------------------------------
__global__ __launch_bounds__(256)
void scores_kernel()
{
    __shared__ float QsT[32][132];
    __shared__ float KsT[32][132];

    const int bh = blockIdx.z;
    const int kx = blockIdx.x * 128;
    const int qy = blockIdx.y * 128;
    const int tid = threadIdx.x;
    const int tx = tid & 15, ty = tid >> 4;

    float acc[8][8];
#pragma unroll
    for (int i = 0; i < 8; i++)
#pragma unroll
        for (int j = 0; j < 8; j++) acc[i][j] = 0.f;

    for (int kb = 0; kb < HD; kb += 32) {
#pragma unroll
        for (int j = 0; j < 4; j++) {
            int i = tid + j * 256;
            int r = i >> 3, c4 = (i & 7) * 4;
            float4 qv = *(const float4*)&g_Qh[((size_t)bh * NN + qy + r) * HD + kb + c4];
            QsT[c4 + 0][r] = qv.x; QsT[c4 + 1][r] = qv.y;
            QsT[c4 + 2][r] = qv.z; QsT[c4 + 3][r] = qv.w;
            float4 kv = *(const float4*)&g_Kh[((size_t)bh * NN + kx + r) * HD + kb + c4];
            KsT[c4 + 0][r] = kv.x; KsT[c4 + 1][r] = kv.y;
            KsT[c4 + 2][r] = kv.z; KsT[c4 + 3][r] = kv.w;
        }
        __syncthreads();
#pragma unroll
        for (int kk = 0; kk < 32; kk++) {
            float4 a0 = *(const float4*)&QsT[kk][ty * 4];
            float4 a1 = *(const float4*)&QsT[kk][64 + ty * 4];
            float4 bv0 = *(const float4*)&KsT[kk][tx * 4];
            float4 bv1 = *(const float4*)&KsT[kk][64 + tx * 4];
            float a[8] = {a0.x, a0.y, a0.z, a0.w, a1.x, a1.y, a1.z, a1.w};
            float b[8] = {bv0.x, bv0.y, bv0.z, bv0.w, bv1.x, bv1.y, bv1.z, bv1.w};
#pragma unroll
            for (int i = 0; i < 8; i++)
#pragma unroll
                for (int j = 0; j < 8; j++) acc[i][j] += a[i] * b[j];
        }
        __syncthreads();
    }

#pragma unroll
    for (int i = 0; i < 8; i++) {
        int row = qy + ((i < 4) ? ty * 4 + i : 64 + ty * 4 + (i - 4));
#pragma unroll
        for (int jg = 0; jg < 2; jg++) {
            int col = kx + ((jg == 0) ? tx * 4 : 64 + tx * 4);
            float4 v = make_float4(acc[i][jg * 4 + 0], acc[i][jg * 4 + 1],
                                   acc[i][jg * 4 + 2], acc[i][jg * 4 + 3]);
            __stcs((float4*)&g_S[((size_t)bh * NN + row) * NN + col], v);
        }
    }
}

// ---------------------------------------------------------------------------
// WARP-PER-ROW topk + softmax + AV. 8 warps/block, one row per warp.
// ONLY change vs round-5: select is 2 radix passes (bits 31:24, 23:16) +
// iterative warp-max resolve in the 16-bit prefix class (exact, dup-safe).
// Natural block order; __ldcs loads; __stcs attn stores. grid 4096 x 256.
// ---------------------------------------------------------------------------
__device__ __forceinline__ float key2float(unsigned k) {
    unsigned u = (k & 0x80000000u) ? (k & 0x7fffffffu) : ~k;
    return __uint_as_float(u);
}

__global__ __launch_bounds__(256)
void topk_av_warp(float* __restrict__ attn, int write_attn)
{
    const int wid  = threadIdx.x >> 5;
    const int lane = threadIdx.x & 31;
    const int row  = blockIdx.x * 8 + wid;    // bh*N + q
    const int bh   = row >> 11;
    const int q    = row & (NN - 1);

    __shared__ int   hist_s[8][256];
    __shared__ int   sidx_s[8][96];
    __shared__ float sw_s[8][96];
    __shared__ int   cnt_s[8];

    int*   hist = hist_s[wid];
    int*   sidx = sidx_s[wid];
    float* sw   = sw_s[wid];

    // ---- load 64 scores/lane as monotone uint keys (coalesced float4) ----
    const float4* Srow = (const float4*)&g_S[(size_t)row * NN];
    unsigned keys[64];
#pragma unroll
    for (int i = 0; i < 16; i++) {
        float4 v = __ldcs(&Srow[i * 32 + lane]);
        float f[4] = {v.x, v.y, v.z, v.w};
#pragma unroll
        for (int j = 0; j < 4; j++) {
            unsigned u = __float_as_uint(f[j]);
            keys[i * 4 + j] = (u & 0x80000000u) ? ~u : (u | 0x80000000u);
        }
    }
    if (lane == 0) cnt_s[wid] = 0;

    // ======== pass 0: 256-bin histogram on bits[31:24] (warp-aggregated) ====
#pragma unroll
    for (int j = 0; j < 8; j++) hist[lane * 8 + j] = 0;
    __syncwarp();
#pragma unroll
    for (int e = 0; e < 64; e++) {
        unsigned bin = keys[e] >> 24;
        unsigned mm = __match_any_sync(0xffffffffu, bin);
        if ((int)(__ffs(mm) - 1) == lane)
            atomicAdd(&hist[bin], __popc(mm));
    }
    __syncwarp();

    int kk = TOPK;
    unsigned B0;
    {
        int h[8], ls[8];
#pragma unroll
        for (int j = 0; j < 8; j++) h[j] = hist[lane * 8 + j];
        int tot = 0;
#pragma unroll
        for (int j = 7; j >= 0; j--) { tot += h[j]; ls[j] = tot; }
        int s = tot;
#pragma unroll
        for (int off = 1; off < 32; off <<= 1) {
            int t = __shfl_down_sync(0xffffffffu, s, off);
            if (lane + off < 32) s += t;
        }
        const int G = s - tot;
        int foundBin = -1, newkk = 0;
#pragma unroll
        for (int j = 0; j < 8; j++) {
            int ge = ls[j] + G;
            int gt = ge - h[j];
            if (ge >= kk && gt < kk && h[j] > 0) {
                foundBin = lane * 8 + j;
                newkk = kk - gt;
            }
        }
        unsigned bal = __ballot_sync(0xffffffffu, foundBin >= 0);
        int src = __ffs(bal) - 1;
        B0 = (unsigned)__shfl_sync(0xffffffffu, foundBin, src);
        kk = __shfl_sync(0xffffffffu, newkk, src);
    }
    __syncwarp();

    // ======== pass 1: bits[23:16] within class B0 ========
#pragma unroll
    for (int j = 0; j < 8; j++) hist[lane * 8 + j] = 0;
    __syncwarp();
#pragma unroll
    for (int e = 0; e < 64; e++) {
        unsigned k = keys[e];
        if ((k >> 24) == B0) atomicAdd(&hist[(k >> 16) & 255u], 1);
    }
    __syncwarp();

    unsigned pref16;
    int m;
    {
        int h[8], ls[8];
#pragma unroll
        for (int j = 0; j < 8; j++) h[j] = hist[lane * 8 + j];
        int tot = 0;
#pragma unroll
        for (int j = 7; j >= 0; j--) { tot += h[j]; ls[j] = tot; }
        int s = tot;
#pragma unroll
        for (int off = 1; off < 32; off <<= 1) {
            int t = __shfl_down_sync(0xffffffffu, s, off);
            if (lane + off < 32) s += t;
        }
        const int G = s - tot;
        int foundBin = -1, newm = 0;
#pragma unroll
        for (int j = 0; j < 8; j++) {
            int ge = ls[j] + G;
            int gt = ge - h[j];
            if (ge >= kk && gt < kk && h[j] > 0) {
                foundBin = lane * 8 + j;
                newm = kk - gt;
            }
        }
        unsigned bal = __ballot_sync(0xffffffffu, foundBin >= 0);
        int src = __ffs(bal) - 1;
        int B1 = __shfl_sync(0xffffffffu, foundBin, src);
        m = __shfl_sync(0xffffffffu, newm, src);
        pref16 = (B0 << 8) | (unsigned)B1;
    }

    // ======== resolve: m-th largest among keys with (key>>16)==pref16 ========
    unsigned kth = 0;
    {
        int need = m;
        unsigned cur = 0xFFFFFFFFu;
        while (true) {
            unsigned mymax = 0u;
#pragma unroll
            for (int e = 0; e < 64; e++) {
                unsigned k = keys[e];
                if ((k >> 16) == pref16 && k < cur && k > mymax) mymax = k;
            }
            unsigned M = mymax;
#pragma unroll
            for (int off = 16; off > 0; off >>= 1) {
                unsigned t = __shfl_xor_sync(0xffffffffu, M, off);
                if (t > M) M = t;
            }
            int c = 0;
#pragma unroll
            for (int e = 0; e < 64; e++) c += (keys[e] == M);
#pragma unroll
            for (int off = 16; off > 0; off >>= 1)
                c += __shfl_xor_sync(0xffffffffu, c, off);
            if (need <= c) { kth = M; break; }
            need -= c;
            cur = M;
        }
    }

    // ---- row max (key order == float order) ----
    unsigned kmax = 0;
#pragma unroll
    for (int e = 0; e < 64; e++) kmax = (keys[e] > kmax) ? keys[e] : kmax;
#pragma unroll
    for (int off = 16; off > 0; off >>= 1) {
        unsigned t = __shfl_xor_sync(0xffffffffu, kmax, off);
        kmax = (t > kmax) ? t : kmax;
    }
    const float rmax = key2float(kmax);

    // ---- sum of exp over selected ----
    float lsum = 0.f;
#pragma unroll
    for (int e = 0; e < 64; e++)
        if (keys[e] >= kth) lsum += __expf(key2float(keys[e]) - rmax);
#pragma unroll
    for (int off = 16; off > 0; off >>= 1)
        lsum += __shfl_xor_sync(0xffffffffu, lsum, off);
    const float inv_z = 1.f / lsum;

    // ---- write attn row + gather selected (idx, w) into warp smem ----
    float4* Arow = (float4*)&attn[(size_t)row * NN];
#pragma unroll
    for (int i = 0; i < 16; i++) {
        float wv[4];
#pragma unroll
        for (int j = 0; j < 4; j++) {
            unsigned k = keys[i * 4 + j];
            bool sel = (k >= kth);
            float w = sel ? __expf(key2float(k) - rmax) * inv_z : 0.f;
            wv[j] = w;
            if (sel) {
                int p = atomicAdd(&cnt_s[wid], 1);
                if (p < 96) { sidx[p] = (i * 32 + lane) * 4 + j; sw[p] = w; }
            }
        }
        if (write_attn)
            __stcs(&Arow[i * 32 + lane], make_float4(wv[0], wv[1], wv[2], wv[3]));
    }
    __syncwarp();
    int cnt = cnt_s[wid]; if (cnt > 96) cnt = 96;

    // ---- AV: 64 dims across 32 lanes (float2/lane), ~64 selected terms ----
    const float2* Vbase = (const float2*)&g_Vh[(size_t)bh * NN * HD];
    float a0 = 0.f, a1 = 0.f;
    for (int j = 0; j < cnt; j++) {
        float wj = sw[j];
        float2 vv = Vbase[(size_t)sidx[j] * 32 + lane];
        a0 += wj * vv.x;
        a1 += wj * vv.y;
    }
    int b = bh >> 3, h = bh & 7;
    float2* Hp = (float2*)&g_H[(size_t)(b * NN + q) * DM + h * HD];
    Hp[lane] = make_float2(a0, a1);
}

// ---------------------------------------------------------------------------
extern "C" void kernel_launch(void* const* d_in, const int* in_sizes, int n_in,
                              void* d_out, int out_size)
{
    const float* q  = (const float*)d_in[0];
    const float* k  = (const float*)d_in[1];
    const float* v  = (const float*)d_in[2];
    const float* wq = (const float*)d_in[3];
    const float* bq = (const float*)d_in[4];
    const float* wk = (const float*)d_in[5];
    const float* bk = (const float*)d_in[6];
    const float* wv = (const float*)d_in[7];
    const float* bv = (const float*)d_in[8];
    const float* wo = (const float*)d_in[9];
    const float* bo = (const float*)d_in[10];

    float* out = (float*)d_out;
    const long long OUT_ELEMS  = (long long)M_TOT * DM;        // 2,097,152
    const long long ATTN_ELEMS = (long long)BH * NN * NN;      // 67,108,864

    int write_attn = 0, write_out = 1;
    float* attn_ptr = nullptr;
    if ((long long)out_size >= OUT_ELEMS + ATTN_ELEMS) {
        write_attn = 1; attn_ptr = out + OUT_ELEMS;
    } else if ((long long)out_size == ATTN_ELEMS) {
        write_attn = 1; attn_ptr = out; write_out = 0;
    }

    gemm128<<<dim3(12, M_TOT / 128), 256>>>(q, k, v, wq, wk, wv, bq, bk, bv,
                                            nullptr, 0);

    scores_kernel<<<dim3(NN / 128, NN / 128, BH), 256>>>();

    topk_av_warp<<<BH * NN / 8, 256>>>(attn_ptr, write_attn);

    if (write_out)
        gemm128<<<dim3(DM / 128, M_TOT / 128), 256>>>(nullptr, nullptr, nullptr,
                                                      wo, nullptr, nullptr,
                                                      bo, nullptr, nullptr,
                                                      out, 1);
}

// round 16
// speedup vs baseline: 1.4617x; 1.4617x over previous
#include <cuda_runtime.h>
#include <math.h>
#include <cstdint>

#define BB 2
#define NN 2048
#define DM 512
#define NH 8
#define HD 64
#define TOPK 64
#define BH (BB*NH)       // 16
#define M_TOT (BB*NN)    // 4096
#define SCALEF 0.125f

// ---------------- scratch (static __device__ per allocation rules) ----------
__device__ float g_Qh[BH*NN*HD];            // [bh][n][d]  (Q pre-scaled by 1/8)
__device__ float g_Kh[BH*NN*HD];
__device__ float g_Vh[BH*NN*HD];
__device__ float g_S[(size_t)BH*NN*NN];     // raw scores 256MB
__device__ float g_H[M_TOT*DM];             // merged-head attn output

// ---------------------------------------------------------------------------
// 128x128-tile fp32 GEMM, 8x8 micro-tile, BK=16, 256 threads, double-buffered.
// mode 0: fused QKV (head-split out, Q scaled). mode 1: out-proj from g_H.
// (round-5 proven version, untouched)
// ---------------------------------------------------------------------------
__global__ __launch_bounds__(256)
void gemm128(const float* __restrict__ X0, const float* __restrict__ X1,
             const float* __restrict__ X2,
             const float* __restrict__ W0, const float* __restrict__ W1,
             const float* __restrict__ W2,
             const float* __restrict__ b0, const float* __restrict__ b1,
             const float* __restrict__ b2,
             float* __restrict__ outp, int mode)
{
    __shared__ float XsT[2][16][132];
    __shared__ float WsT[2][16][132];

    const int tid = threadIdx.x;
    const int tx = tid & 15, ty = tid >> 4;
    const int m0 = blockIdx.y * 128;

    int which = 0, o0 = 0;
    const float *X, *W, *bias;
    if (mode == 0) {
        which = blockIdx.x >> 2;
        o0 = (blockIdx.x & 3) * 128;
        X    = (which == 0) ? X0 : (which == 1) ? X1 : X2;
        W    = (which == 0) ? W0 : (which == 1) ? W1 : W2;
        bias = (which == 0) ? b0 : (which == 1) ? b1 : b2;
    } else {
        o0 = blockIdx.x * 128;
        X = g_H; W = W0; bias = b0;
    }

    const int lr  = tid >> 2;
    const int lc4 = (tid & 3) * 4;

    float acc[8][8];
#pragma unroll
    for (int i = 0; i < 8; i++)
#pragma unroll
        for (int j = 0; j < 8; j++) acc[i][j] = 0.f;

    float4 xr[2], wr[2];
#pragma unroll
    for (int j = 0; j < 2; j++) {
        int r = lr + j * 64;
        xr[j] = *(const float4*)&X[(size_t)(m0 + r) * DM + lc4];
        wr[j] = *(const float4*)&W[(size_t)(o0 + r) * DM + lc4];
    }
#pragma unroll
    for (int j = 0; j < 2; j++) {
        int r = lr + j * 64;
        XsT[0][lc4 + 0][r] = xr[j].x; XsT[0][lc4 + 1][r] = xr[j].y;
        XsT[0][lc4 + 2][r] = xr[j].z; XsT[0][lc4 + 3][r] = xr[j].w;
        WsT[0][lc4 + 0][r] = wr[j].x; WsT[0][lc4 + 1][r] = wr[j].y;
        WsT[0][lc4 + 2][r] = wr[j].z; WsT[0][lc4 + 3][r] = wr[j].w;
    }
    __syncthreads();

    int p = 0;
    for (int k0 = 0; k0 < DM; k0 += 16) {
        const int kn = k0 + 16;
        if (kn < DM) {
#pragma unroll
            for (int j = 0; j < 2; j++) {
                int r = lr + j * 64;
                xr[j] = *(const float4*)&X[(size_t)(m0 + r) * DM + kn + lc4];
                wr[j] = *(const float4*)&W[(size_t)(o0 + r) * DM + kn + lc4];
            }
        }
#pragma unroll
        for (int kk = 0; kk < 16; kk++) {
            float4 a0 = *(const float4*)&XsT[p][kk][ty * 4];
            float4 a1 = *(const float4*)&XsT[p][kk][64 + ty * 4];
            float4 bv0 = *(const float4*)&WsT[p][kk][tx * 4];
            float4 bv1 = *(const float4*)&WsT[p][kk][64 + tx * 4];
            float a[8] = {a0.x, a0.y, a0.z, a0.w, a1.x, a1.y, a1.z, a1.w};
            float b[8] = {bv0.x, bv0.y, bv0.z, bv0.w, bv1.x, bv1.y, bv1.z, bv1.w};
#pragma unroll
            for (int i = 0; i < 8; i++)
#pragma unroll
                for (int j = 0; j < 8; j++) acc[i][j] += a[i] * b[j];
        }
        if (kn < DM) {
            int pn = p ^ 1;
#pragma unroll
            for (int j = 0; j < 2; j++) {
                int r = lr + j * 64;
                XsT[pn][lc4 + 0][r] = xr[j].x; XsT[pn][lc4 + 1][r] = xr[j].y;
                XsT[pn][lc4 + 2][r] = xr[j].z; XsT[pn][lc4 + 3][r] = xr[j].w;
                WsT[pn][lc4 + 0][r] = wr[j].x; WsT[pn][lc4 + 1][r] = wr[j].y;
                WsT[pn][lc4 + 2][r] = wr[j].z; WsT[pn][lc4 + 3][r] = wr[j].w;
            }
        }
        __syncthreads();
        p ^= 1;
    }

    const float sc = (mode == 0 && which == 0) ? SCALEF : 1.f;
#pragma unroll
    for (int i = 0; i < 8; i++) {
        int m = m0 + ((i < 4) ? ty * 4 + i : 64 + ty * 4 + (i - 4));
#pragma unroll
        for (int jg = 0; jg < 2; jg++) {
            int oc = o0 + ((jg == 0) ? tx * 4 : 64 + tx * 4);
            float4 v;
            v.x = (acc[i][jg * 4 + 0] + bias[oc + 0]) * sc;
            v.y = (acc[i][jg * 4 + 1] + bias[oc + 1]) * sc;
            v.z = (acc[i][jg * 4 + 2] + bias[oc + 2]) * sc;
            v.w = (acc[i][jg * 4 + 3] + bias[oc + 3]) * sc;
            if (mode == 0) {
                int b = m >> 11, n = m & (NN - 1);
                int h = oc >> 6, d = oc & 63;
                float* dst = (which == 0) ? g_Qh : (which == 1) ? g_Kh : g_Vh;
                *(float4*)&dst[(size_t)((b * NH + h) * NN + n) * HD + d] = v;
            } else {
                *(float4*)&outp[(size_t)m * DM + oc] = v;
            }
        }
    }
}

// ---------------------------------------------------------------------------
// Scores (round-5 proven, untouched): S = Qh @ Kh^T. 128x128 tiles,
// 8x8 micro-tile, 2 x BK=32 stages, __stcs streaming stores. grid (16,16,16).
// ---------------------------------------------------------------------------
__global__ __launch_bounds__(256)
void scores_kernel()
{
    __shared__ float QsT[32][132];
    __shared__ float KsT[32][132];

    const int bh = blockIdx.z;
    const int kx = blockIdx.x * 128;
    const int qy = blockIdx.y * 128;
    const int tid = threadIdx.x;
    const int tx = tid & 15, ty = tid >> 4;

    float acc[8][8];
#pragma unroll
    for (int i = 0; i < 8; i++)
#pragma unroll
        for (int j = 0; j < 8; j++) acc[i][j] = 0.f;

    for (int kb = 0; kb < HD; kb += 32) {
#pragma unroll
        for (int j = 0; j < 4; j++) {
            int i = tid + j * 256;
            int r = i >> 3, c4 = (i & 7) * 4;
            float4 qv = *(const float4*)&g_Qh[((size_t)bh * NN + qy + r) * HD + kb + c4];
            QsT[c4 + 0][r] = qv.x; QsT[c4 + 1][r] = qv.y;
            QsT[c4 + 2][r] = qv.z; QsT[c4 + 3][r] = qv.w;
            float4 kv = *(const float4*)&g_Kh[((size_t)bh * NN + kx + r) * HD + kb + c4];
            KsT[c4 + 0][r] = kv.x; KsT[c4 + 1][r] = kv.y;
            KsT[c4 + 2][r] = kv.z; KsT[c4 + 3][r] = kv.w;
        }
        __syncthreads();
#pragma unroll
        for (int kk = 0; kk < 32; kk++) {
            float4 a0 = *(const float4*)&QsT[kk][ty * 4];
            float4 a1 = *(const float4*)&QsT[kk][64 + ty * 4];
            float4 bv0 = *(const float4*)&KsT[kk][tx * 4];
            float4 bv1 = *(const float4*)&KsT[kk][64 + tx * 4];
            float a[8] = {a0.x, a0.y, a0.z, a0.w, a1.x, a1.y, a1.z, a1.w};
            float b[8] = {bv0.x, bv0.y, bv0.z, bv0.w, bv1.x, bv1.y, bv1.z, bv1.w};
#pragma unroll
            for (int i = 0; i < 8; i++)
#pragma unroll
                for (int j = 0; j < 8; j++) acc[i][j] += a[i] * b[j];
        }
        __syncthreads();
    }

#pragma unroll
    for (int i = 0; i < 8; i++) {
        int row = qy + ((i < 4) ? ty * 4 + i : 64 + ty * 4 + (i - 4));
#pragma unroll
        for (int jg = 0; jg < 2; jg++) {
            int col = kx + ((jg == 0) ? tx * 4 : 64 + tx * 4);
            float4 v = make_float4(acc[i][jg * 4 + 0], acc[i][jg * 4 + 1],
                                   acc[i][jg * 4 + 2], acc[i][jg * 4 + 3]);
            __stcs((float4*)&g_S[((size_t)bh * NN + row) * NN + col], v);
        }
    }
}

// ---------------------------------------------------------------------------
// WARP-PER-ROW topk + softmax + AV. 8 warps/block, one row per warp.
// Select: round-5 proven 4x8-bit MSB radix (frozen).
// ONLY change vs r5: exp computed ONLY for the <=96 gathered selected
// entries (3 MUFU/lane instead of ~128); attn row written as zero-fill +
// fence + scatter of the selected weights.  grid 4096 x 256.
// ---------------------------------------------------------------------------
__device__ __forceinline__ float key2float(unsigned k) {
    unsigned u = (k & 0x80000000u) ? (k & 0x7fffffffu) : ~k;
    return __uint_as_float(u);
}

__global__ __launch_bounds__(256)
void topk_av_warp(float* __restrict__ attn, int write_attn)
{
    const int wid  = threadIdx.x >> 5;
    const int lane = threadIdx.x & 31;
    const int row  = blockIdx.x * 8 + wid;    // bh*N + q
    const int bh   = row >> 11;
    const int q    = row & (NN - 1);

    __shared__ int   hist_s[8][256];
    __shared__ int   sidx_s[8][96];
    __shared__ float sw_s[8][96];
    __shared__ int   cnt_s[8];

    int*   hist = hist_s[wid];
    int*   sidx = sidx_s[wid];
    float* sw   = sw_s[wid];

    // ---- load 64 scores/lane as monotone uint keys (coalesced float4) ----
    const float4* Srow = (const float4*)&g_S[(size_t)row * NN];
    unsigned keys[64];
#pragma unroll
    for (int i = 0; i < 16; i++) {
        float4 v = __ldcs(&Srow[i * 32 + lane]);
        float f[4] = {v.x, v.y, v.z, v.w};
#pragma unroll
        for (int j = 0; j < 4; j++) {
            unsigned u = __float_as_uint(f[j]);
            keys[i * 4 + j] = (u & 0x80000000u) ? ~u : (u | 0x80000000u);
        }
    }
    if (lane == 0) cnt_s[wid] = 0;

    // ---- exact 64th-largest via 4 x 8-bit MSB radix passes (r5 frozen) ----
    unsigned prefix = 0;
    int kk = TOPK;
    for (int pass = 0; pass < 4; pass++) {
        const int shift = 24 - 8 * pass;
#pragma unroll
        for (int j = 0; j < 8; j++) hist[lane * 8 + j] = 0;
        __syncwarp();

        if (pass == 0) {
#pragma unroll
            for (int e = 0; e < 64; e++) {
                unsigned bin = keys[e] >> 24;
                unsigned mm = __match_any_sync(0xffffffffu, bin);
                if ((int)(__ffs(mm) - 1) == lane)
                    atomicAdd(&hist[bin], __popc(mm));
            }
        } else {
#pragma unroll
            for (int e = 0; e < 64; e++) {
                unsigned k = keys[e];
                unsigned hi = (k >> (31 - 8 * pass)) >> 1;
                if (hi == prefix) atomicAdd(&hist[(k >> shift) & 255u], 1);
            }
        }
        __syncwarp();

        int h[8], ls[8];
#pragma unroll
        for (int j = 0; j < 8; j++) h[j] = hist[lane * 8 + j];
        int tot = 0;
#pragma unroll
        for (int j = 7; j >= 0; j--) { tot += h[j]; ls[j] = tot; }
        int s = tot;
#pragma unroll
        for (int off = 1; off < 32; off <<= 1) {
            int t = __shfl_down_sync(0xffffffffu, s, off);
            if (lane + off < 32) s += t;
        }
        const int G = s - tot;
        int foundBin = -1, newkk = 0;
#pragma unroll
        for (int j = 0; j < 8; j++) {
            int ge = ls[j] + G;
            int gt = ge - h[j];
            if (ge >= kk && gt < kk && h[j] > 0) {
                foundBin = lane * 8 + j;
                newkk = kk - gt;
            }
        }
        unsigned bal = __ballot_sync(0xffffffffu, foundBin >= 0);
        int src = __ffs(bal) - 1;
        foundBin = __shfl_sync(0xffffffffu, foundBin, src);
        newkk    = __shfl_sync(0xffffffffu, newkk, src);
        prefix = (prefix << 8) | (unsigned)foundBin;
        kk = newkk;
        __syncwarp();
    }
    const unsigned kth = prefix;

    // ---- row max (key order == float order) ----
    unsigned kmax = 0;
#pragma unroll
    for (int e = 0; e < 64; e++) kmax = (keys[e] > kmax) ? keys[e] : kmax;
#pragma unroll
    for (int off = 16; off > 0; off >>= 1) {
        unsigned t = __shfl_xor_sync(0xffffffffu, kmax, off);
        kmax = (t > kmax) ? t : kmax;
    }
    const float rmax = key2float(kmax);

    // ---- Phase A: gather selected (idx, raw key) — NO exp here ----
#pragma unroll
    for (int i = 0; i < 16; i++) {
#pragma unroll
        for (int j = 0; j < 4; j++) {
            unsigned k = keys[i * 4 + j];
            if (k >= kth) {
                int p = atomicAdd(&cnt_s[wid], 1);
                if (p < 96) {
                    sidx[p] = (i * 32 + lane) * 4 + j;
                    sw[p] = __uint_as_float(k);   // stash key bits
                }
            }
        }
    }
    __syncwarp();
    int cnt = cnt_s[wid]; if (cnt > 96) cnt = 96;

    // ---- Phase B: exp only on gathered (<=3/lane), Z, normalize in place ----
    float part = 0.f;
    for (int j = lane; j < cnt; j += 32) {
        float e = __expf(key2float(__float_as_uint(sw[j])) - rmax);
        sw[j] = e;
        part += e;
    }
#pragma unroll
    for (int off = 16; off > 0; off >>= 1)
        part += __shfl_xor_sync(0xffffffffu, part, off);
    const float inv_z = 1.f / part;
    __syncwarp();
    for (int j = lane; j < cnt; j += 32) sw[j] *= inv_z;
    __syncwarp();

    // ---- Phase C: attn row = zeros, then scatter selected weights ----
    if (write_attn) {
        float4* Arow4 = (float4*)&attn[(size_t)row * NN];
        const float4 z4 = make_float4(0.f, 0.f, 0.f, 0.f);
#pragma unroll
        for (int i = 0; i < 16; i++)
            __stcs(&Arow4[i * 32 + lane], z4);
        __threadfence_block();
        __syncwarp();
        float* Arow = &attn[(size_t)row * NN];
        for (int j = lane; j < cnt; j += 32)
            Arow[sidx[j]] = sw[j];
    }

    // ---- AV: 64 dims across 32 lanes (float2/lane), ~64 selected terms ----
    const float2* Vbase = (const float2*)&g_Vh[(size_t)bh * NN * HD];
    float a0 = 0.f, a1 = 0.f;
    for (int j = 0; j < cnt; j++) {
        float wj = sw[j];
        float2 vv = Vbase[(size_t)sidx[j] * 32 + lane];
        a0 += wj * vv.x;
        a1 += wj * vv.y;
    }
    int b = bh >> 3, h = bh & 7;
    float2* Hp = (float2*)&g_H[(size_t)(b * NN + q) * DM + h * HD];
    Hp[lane] = make_float2(a0, a1);
}

// ---------------------------------------------------------------------------
extern "C" void kernel_launch(void* const* d_in, const int* in_sizes, int n_in,
                              void* d_out, int out_size)
{
    const float* q  = (const float*)d_in[0];
    const float* k  = (const float*)d_in[1];
    const float* v  = (const float*)d_in[2];
    const float* wq = (const float*)d_in[3];
    const float* bq = (const float*)d_in[4];
    const float* wk = (const float*)d_in[5];
    const float* bk = (const float*)d_in[6];
    const float* wv = (const float*)d_in[7];
    const float* bv = (const float*)d_in[8];
    const float* wo = (const float*)d_in[9];
    const float* bo = (const float*)d_in[10];

    float* out = (float*)d_out;
    const long long OUT_ELEMS  = (long long)M_TOT * DM;        // 2,097,152
    const long long ATTN_ELEMS = (long long)BH * NN * NN;      // 67,108,864

    int write_attn = 0, write_out = 1;
    float* attn_ptr = nullptr;
    if ((long long)out_size >= OUT_ELEMS + ATTN_ELEMS) {
        write_attn = 1; attn_ptr = out + OUT_ELEMS;
    } else if ((long long)out_size == ATTN_ELEMS) {
        write_attn = 1; attn_ptr = out; write_out = 0;
    }

    gemm128<<<dim3(12, M_TOT / 128), 256>>>(q, k, v, wq, wk, wv, bq, bk, bv,
                                            nullptr, 0);

    scores_kernel<<<dim3(NN / 128, NN / 128, BH), 256>>>();

    topk_av_warp<<<BH * NN / 8, 256>>>(attn_ptr, write_attn);

    if (write_out)
        gemm128<<<dim3(DM / 128, M_TOT / 128), 256>>>(nullptr, nullptr, nullptr,
                                                      wo, nullptr, nullptr,
                                                      bo, nullptr, nullptr,
                                                      out, 1);
}